// round 12
// baseline (speedup 1.0000x reference)
#include <cuda_runtime.h>
#include <cstdint>

#define NNODES 65536
#define NPART  128
#define EPSV   1e-8f
#define BIGV   999.0f

// ---- output layout (flattened f32, reference tuple order) ----
#define OFF_RMS    0
#define OFF_RMSQ   128
#define OFF_NP     256
#define OFF_NN     384
#define OFF_RMSG   1024
#define OFF_RMSQG  1025
#define OFF_NG     1026
#define OFF_NNG    1027
#define OFF_DB     1032
#define OFF_NNODE  1033
#define OFF_DIST   66569
#define OFF_BEL    8455177

// belongs region: [OFF_BEL, OFF_BEL + 128*65536). OFF_BEL % 4 == 1 ->
// head of 3 scalars, 2097151 aligned float4s, tail of 1 scalar.
#define BEL_Q4     2097151
#define NCHUNK     256     // node-pair chunks (256 acc blocks x 128 pair-threads)
#define NPCHUNK    4       // particle-row chunks for dist blocks
#define NBELBLK    512     // belongs fill blocks

// ---- device scratch (k_init zeroes only the cheap int atomics) ----
__device__ float  g_part_scal[NCHUNK][8];       // plain stores, no init needed
__device__ float  g_part_dx2[NCHUNK * NPART];   // chunk-major, coalesced stores, no init
__device__ int    g_cnt[NPART];                 // int atomics (k_init zeroes)
__device__ int    g_ncond;                      // int atomic  (k_init zeroes)
__device__ float4 g_condx[NNODES];              // globally compacted, contiguous

__device__ __forceinline__ float fsqrt_ap(float x) {
    float r; asm("sqrt.approx.f32 %0, %1;" : "=f"(r) : "f"(x)); return r;
}

// ---------------------------------------------------------------------------
__global__ void k_init() {
    int t = threadIdx.x;
    if (t < NPART) g_cnt[t] = 0;
    if (t == 0)    g_ncond = 0;
}

// ---------------------------------------------------------------------------
// k_main, grid = 1536 x 128 threads:
//   blocks [0,1024):    dist. chunk = b & 255 (128 node pairs), pc = b >> 8
//                       (32 particle rows). pc==0 blocks also accumulate.
//   blocks [1024,1536): belongs fill: aligned float4 stores of (parent[n]==p).
__global__ void __launch_bounds__(128)
k_main(const float* __restrict__ x, const float* __restrict__ q,
       const float* __restrict__ ic, const float* __restrict__ maxx,
       const int* __restrict__ parent, float* __restrict__ out) {
    const int b = blockIdx.x, t = threadIdx.x;

    if (b >= NPCHUNK * NCHUNK) {
        // ---------------- belongs fill ----------------
        const int f = (b - NPCHUNK * NCHUNK) * 128 + t;   // [0, 65536)
        float4* dst4 = (float4*)(out + OFF_BEL + 3);
        #pragma unroll 4
        for (int k = 0; k < 32; k++) {
            const int i = f + (k << 16);
            if (i >= BEL_Q4) break;
            const int j = 3 + 4 * i;
            const int p = j >> 16;
            const int n = j & 65535;      // n == 3 (mod 4)
            float4 v;
            if (n < 65535) {
                const int  pn = __ldg(parent + n);
                const int4 p4 = __ldg((const int4*)(parent + n + 1));
                v.x = (pn   == p) ? 1.f : 0.f;
                v.y = (p4.x == p) ? 1.f : 0.f;
                v.z = (p4.y == p) ? 1.f : 0.f;
                v.w = (p4.z == p) ? 1.f : 0.f;
            } else {                      // crosses row boundary: (p,65535),(p+1,0..2)
                v.x = (__ldg(parent + 65535) == p)     ? 1.f : 0.f;
                v.y = (__ldg(parent + 0)     == p + 1) ? 1.f : 0.f;
                v.z = (__ldg(parent + 1)     == p + 1) ? 1.f : 0.f;
                v.w = (__ldg(parent + 2)     == p + 1) ? 1.f : 0.f;
            }
            dst4[i] = v;
        }
        if (b == NPCHUNK * NCHUNK && t == 0) {   // head (p=0,n=0..2) + tail (p=127,n=65535)
            out[OFF_BEL + 0] = (__ldg(parent + 0) == 0) ? 1.f : 0.f;
            out[OFF_BEL + 1] = (__ldg(parent + 1) == 0) ? 1.f : 0.f;
            out[OFF_BEL + 2] = (__ldg(parent + 2) == 0) ? 1.f : 0.f;
            out[OFF_BEL + NPART * NNODES - 1] = (__ldg(parent + NNODES - 1) == 127) ? 1.f : 0.f;
        }
        return;
    }

    // ---------------- dist blocks ----------------
    __shared__ float sm0[NPART], sm1[NPART], sm2[NPART];
    __shared__ float sdx2[NPART];
    __shared__ int   scnt[NPART];
    __shared__ int   s_cc, s_base;
    __shared__ float4 s_cond[256];
    __shared__ float swp[4][7];

    const int chunk = b & (NCHUNK - 1);
    const int pc    = b >> 8;
    const bool acc  = (pc == 0);

    sm0[t] = maxx[3 * t + 0];
    sm1[t] = maxx[3 * t + 1];
    sm2[t] = maxx[3 * t + 2];
    if (acc) { sdx2[t] = 0.f; scnt[t] = 0; if (t == 0) s_cc = 0; }
    __syncthreads();

    const int  g = chunk * 128 + t;
    const bool paired = (g < NCHUNK * 128 - 1);
    const int  na = paired ? 2 * g + 1 : 0;
    const int  nb = paired ? 2 * g + 2 : NNODES - 1;

    const float a0 = x[3 * na], a1 = x[3 * na + 1], a2 = x[3 * na + 2];
    const float b0 = x[3 * nb], b1 = x[3 * nb + 1], b2 = x[3 * nb + 2];

    if (acc) {
        const int   pa = parent[na], pb = parent[nb];
        const float qa = q[na], qb = q[nb];
        const float ia = ic[na], ib = ic[nb];
        const float nxa = fmaf(a2, a2, fmaf(a1, a1, a0 * a0));
        const float nxb = fmaf(b2, b2, fmaf(b1, b1, b0 * b0));
        const float q2a = qa * qa, q2b = qb * qb;

        float d0 = a0 - sm0[pa], d1 = a1 - sm1[pa], d2 = a2 - sm2[pa];
        atomicAdd(&sdx2[pa], fmaf(d2, d2, fmaf(d1, d1, d0 * d0)));  // native shared f32
        atomicAdd(&scnt[pa], 1);
        d0 = b0 - sm0[pb]; d1 = b1 - sm1[pb]; d2 = b2 - sm2[pb];
        atomicAdd(&sdx2[pb], fmaf(d2, d2, fmaf(d1, d1, d0 * d0)));
        atomicAdd(&scnt[pb], 1);

        if (ia > 0.f) { int p_ = atomicAdd(&s_cc, 1); s_cond[p_] = make_float4(a0, a1, a2, 0.f); }
        if (ib > 0.f) { int p_ = atomicAdd(&s_cc, 1); s_cond[p_] = make_float4(b0, b1, b2, 0.f); }

        float v[7] = { qa + qb, q2a + q2b,
                       fmaf(q2a, nxa, q2b * nxb),
                       fmaf(q2a, a0, q2b * b0),
                       fmaf(q2a, a1, q2b * b1),
                       fmaf(q2a, a2, q2b * b2),
                       nxa + nxb };
        #pragma unroll
        for (int k = 0; k < 7; k++) {
            float s = v[k];
            #pragma unroll
            for (int o = 16; o > 0; o >>= 1) s += __shfl_xor_sync(0xffffffffu, s, o);
            v[k] = s;
        }
        if ((t & 31) == 0) {
            #pragma unroll
            for (int k = 0; k < 7; k++) swp[t >> 5][k] = v[k];
        }
    }

    // ---- dist_edge: 32 rows, float2 per thread (aligned: na odd) ----
    float* dbase = out + OFF_DIST;
    const int p0 = pc * 32;
    if (paired) {
        #pragma unroll 4
        for (int pp = 0; pp < 32; pp++) {
            const int p = p0 + pp;
            const float m0 = sm0[p], m1 = sm1[p], m2 = sm2[p];
            float d0 = a0 - m0, d1 = a1 - m1, d2 = a2 - m2;
            const float da = fsqrt_ap(fmaf(d2, d2, fmaf(d1, d1, d0 * d0)));
            d0 = b0 - m0; d1 = b1 - m1; d2 = b2 - m2;
            const float db_ = fsqrt_ap(fmaf(d2, d2, fmaf(d1, d1, d0 * d0)));
            *(float2*)(dbase + p * NNODES + na) = make_float2(da, db_);
        }
    } else {
        for (int pp = 0; pp < 32; pp++) {
            const int p = p0 + pp;
            const float m0 = sm0[p], m1 = sm1[p], m2 = sm2[p];
            float d0 = a0 - m0, d1 = a1 - m1, d2 = a2 - m2;
            dbase[p * NNODES + na] = fsqrt_ap(fmaf(d2, d2, fmaf(d1, d1, d0 * d0)));
            d0 = b0 - m0; d1 = b1 - m1; d2 = b2 - m2;
            dbase[p * NNODES + nb] = fsqrt_ap(fmaf(d2, d2, fmaf(d1, d1, d0 * d0)));
        }
    }

    if (acc) {
        __syncthreads();
        if (t == 0) {
            #pragma unroll
            for (int k = 0; k < 7; k++)
                g_part_scal[chunk][k] = swp[0][k] + swp[1][k] + swp[2][k] + swp[3][k];
            s_base = (s_cc > 0) ? atomicAdd(&g_ncond, s_cc) : 0;
        }
        // dx2: unconditional coalesced partial store (no f64 atomics)
        g_part_dx2[chunk * NPART + t] = sdx2[t];
        // counts: cheap native int atomics
        atomicAdd(&g_cnt[t], scnt[t]);
        __syncthreads();
        const int cc = s_cc, base = s_base;
        if (t < cc) g_condx[base + t] = s_cond[t];
        if (t + 128 < cc) g_condx[base + t + 128] = s_cond[t + 128];
    }
}

// ---------------------------------------------------------------------------
// k_post, grid = 386 x 256 (proven R8 structure):
//   blocks [0,129):   top-5 over contiguous compacted cond points (b==128: global, m=0)
//   block  129:       finalize (now also reduces the dx2 partials, coalesced)
//   blocks [130,386): N_node gather (direct g_cnt reads)
__global__ void __launch_bounds__(256)
k_post(const float* __restrict__ maxx, const float* __restrict__ maxq,
       const int* __restrict__ parent, float* __restrict__ out) {
    const int b = blockIdx.x, t = threadIdx.x;

    if (b < NPART + 1) {
        // ---------------- top-5: contiguous coalesced scan ----------------
        float m0 = 0.f, m1 = 0.f, m2 = 0.f;
        if (b < NPART) { m0 = maxx[3 * b]; m1 = maxx[3 * b + 1]; m2 = maxx[3 * b + 2]; }
        const int nc = g_ncond;

        float tv[5] = { BIGV, BIGV, BIGV, BIGV, BIGV };
        for (int i = t; i < nc; i += 256) {
            const float4 c = g_condx[i];
            const float d0 = c.x - m0, d1 = c.y - m1, d2 = c.z - m2;
            const float d = fsqrt_ap(fmaf(d2, d2, fmaf(d1, d1, d0 * d0)));
            if (d >= EPSV && d < tv[4]) {
                tv[4] = d;
                #pragma unroll
                for (int k = 4; k > 0; k--)
                    if (tv[k] < tv[k - 1]) { float tmp = tv[k - 1]; tv[k - 1] = tv[k]; tv[k] = tmp; }
            }
        }

        __shared__ float s[256 * 5];
        #pragma unroll
        for (int k = 0; k < 5; k++) s[t * 5 + k] = tv[k];
        __syncthreads();
        for (int str = 128; str >= 1; str >>= 1) {
            if (t < str) {
                float A[5], B[5], R[5];
                #pragma unroll
                for (int k = 0; k < 5; k++) { A[k] = s[t * 5 + k]; B[k] = s[(t + str) * 5 + k]; }
                int ja = 0, jb = 0;
                #pragma unroll
                for (int k = 0; k < 5; k++) R[k] = (A[ja] <= B[jb]) ? A[ja++] : B[jb++];
                #pragma unroll
                for (int k = 0; k < 5; k++) s[t * 5 + k] = R[k];
            }
            __syncthreads();
        }
        if (t == 0) {
            float* dst = (b < NPART) ? (out + OFF_NN + b * 5) : (out + OFF_NNG);
            #pragma unroll
            for (int k = 0; k < 5; k++) dst[k] = s[k];
        }
    } else if (b == NPART + 1) {
        // ---------------- finalize ----------------
        __shared__ double sscal[7];
        __shared__ double sdxa[256];
        __shared__ double sdx2sh[NPART];
        __shared__ float  srms[NPART], sx0[NPART], sx1[NPART], sx2[NPART], sred[NPART];

        // dx2 partial reduce: 2 groups x 128 particles; reads coalesced
        // (128 consecutive floats per chunk line), double accumulation.
        {
            const int p = t & 127, grp = t >> 7;     // grp in {0,1}
            double acc2 = 0.0;
            #pragma unroll 8
            for (int c = grp * 128; c < grp * 128 + 128; c++)
                acc2 += (double)g_part_dx2[c * NPART + p];
            sdxa[t] = acc2;
        }
        // scalar partials: warp w reduces scalar w over 256 chunks
        const int w = t >> 5, l = t & 31;
        if (w < 7) {
            float facc = 0.f;
            #pragma unroll
            for (int r = 0; r < 8; r++) facc += g_part_scal[l + 32 * r][w];
            double acc = (double)facc;
            #pragma unroll
            for (int o = 16; o > 0; o >>= 1)
                acc += __shfl_xor_sync(0xffffffffu, acc, o);
            if (l == 0) sscal[w] = acc;
        }
        __syncthreads();
        if (t < NPART) sdx2sh[t] = sdxa[t] + sdxa[t + 128];
        __syncthreads();

        const double sumq = sscal[0], Bq = sscal[1], A = sscal[2];
        const double C0 = sscal[3], C1 = sscal[4], C2 = sscal[5], snx2 = sscal[6];

        if (t < NPART) {
            const float m0 = maxx[3 * t], m1 = maxx[3 * t + 1], m2 = maxx[3 * t + 2];
            const int   cnt = g_cnt[t];
            const double Npd = (double)cnt;
            const double mp2 = (double)m0 * m0 + (double)m1 * m1 + (double)m2 * m2;
            const double S = A + mp2 * Bq - 2.0 * ((double)m0 * C0 + (double)m1 * C1 + (double)m2 * C2);
            const float rms = (float)sqrt(sdx2sh[t] / Npd);
            const double mq = (double)maxq[t];
            // particle-case sum_q quirk: whole [P,N] mailbox = P * sum(q)
            const float rmsq = (float)sqrt(mq * mq * S / (Npd * ((double)NPART * sumq)));
            out[OFF_RMS  + t] = rms;
            out[OFF_RMSQ + t] = rmsq;
            out[OFF_NP   + t] = (float)cnt;
            srms[t] = rms; sx0[t] = m0; sx1[t] = m1; sx2[t] = m2;
        }
        __syncthreads();

        if (t < NPART) {
            float maxR = 0.f;
            for (int j = 0; j < NPART; j++) {
                const float e0 = sx0[t] - sx0[j], e1 = sx1[t] - sx1[j], e2 = sx2[t] - sx2[j];
                const float M2 = fmaf(e2, e2, fmaf(e1, e1, e0 * e0));
                if (M2 > 0.f) maxR = fmaxf(maxR, (srms[t] + srms[j]) / M2);
            }
            sred[t] = maxR;
        }
        __syncthreads();
        for (int str = 64; str >= 1; str >>= 1) {
            if (t < str) sred[t] += sred[t + str];
            __syncthreads();
        }
        if (t == 0) {
            out[OFF_DB]    = sred[0] / (float)NPART;
            out[OFF_RMSG]  = (float)sqrt(snx2 / (double)NNODES);
            out[OFF_RMSQG] = (float)sqrt(A / ((double)NNODES * sumq));
            out[OFF_NG]    = (float)NNODES;
        }
    } else {
        // ---------------- N_node gather (direct g_cnt reads) ----------------
        const int n = (b - (NPART + 2)) * 256 + t;
        out[OFF_NNODE + n] = (float)g_cnt[parent[n]];
    }
}

// ---------------------------------------------------------------------------
extern "C" void kernel_launch(void* const* d_in, const int* in_sizes, int n_in,
                              void* d_out, int out_size) {
    const float* x      = (const float*)d_in[0];
    const float* q      = (const float*)d_in[1];
    const float* ic     = (const float*)d_in[2];
    const float* maxx   = (const float*)d_in[5];
    const float* maxq   = (const float*)d_in[6];
    const int*   parent = (const int*)d_in[8];
    float* out = (float*)d_out;

    k_init<<<1, 128>>>();
    k_main<<<NPCHUNK * NCHUNK + NBELBLK, 128>>>(x, q, ic, maxx, parent, out);
    k_post<<<NPART + 2 + NNODES / 256, 256>>>(maxx, maxq, parent, out);
    (void)in_sizes; (void)n_in; (void)out_size;
}

// round 13
// speedup vs baseline: 1.2100x; 1.2100x over previous
#include <cuda_runtime.h>
#include <cstdint>

#define NNODES 65536
#define NPART  128
#define EPSV   1e-8f
#define BIGV   999.0f

// ---- output layout (flattened f32, reference tuple order) ----
#define OFF_RMS    0
#define OFF_RMSQ   128
#define OFF_NP     256
#define OFF_NN     384
#define OFF_RMSG   1024
#define OFF_RMSQG  1025
#define OFF_NG     1026
#define OFF_NNG    1027
#define OFF_DB     1032
#define OFF_NNODE  1033
#define OFF_DIST   66569
#define OFF_BEL    8455177

// belongs region: [OFF_BEL, OFF_BEL + 128*65536). OFF_BEL % 4 == 1 ->
// head of 3 scalars, 2097151 aligned float4s, tail of 1 scalar.
#define BEL_Q4     2097151
#define NCHUNK     256     // node-pair chunks (256 acc blocks x 128 pair-threads)
#define NPCHUNK    4       // particle-row chunks for dist blocks
#define NBELBLK    512     // belongs fill blocks

// ---- device scratch (k_init zeroes the atomic accumulators) ----
__device__ float  g_part_scal[NCHUNK][8];  // plain stores: [0]=sum q [1]=q^2 [2]=A [3..5]=C [6]=|x|^2
__device__ double g_sumdx2[NPART];
__device__ int    g_cnt[NPART];
__device__ int    g_ncond;
__device__ float4 g_condx[NNODES];         // globally compacted, contiguous

__device__ __forceinline__ float fsqrt_ap(float x) {
    float r; asm("sqrt.approx.f32 %0, %1;" : "=f"(r) : "f"(x)); return r;
}

// ---------------------------------------------------------------------------
__global__ void k_init() {
    int t = threadIdx.x;
    if (t < NPART) { g_sumdx2[t] = 0.0; g_cnt[t] = 0; }
    if (t == 0)    g_ncond = 0;
}

// ---------------------------------------------------------------------------
// k_main, grid = 1536 x 128 threads (identical to the proven 34.2us version):
//   blocks [0,1024):    dist. chunk = b & 255 (128 node pairs), pc = b >> 8
//                       (32 particle rows). pc==0 blocks also accumulate.
//   blocks [1024,1536): belongs fill: aligned float4 stores of (parent[n]==p).
__global__ void __launch_bounds__(128)
k_main(const float* __restrict__ x, const float* __restrict__ q,
       const float* __restrict__ ic, const float* __restrict__ maxx,
       const int* __restrict__ parent, float* __restrict__ out) {
    const int b = blockIdx.x, t = threadIdx.x;

    if (b >= NPCHUNK * NCHUNK) {
        // ---------------- belongs fill ----------------
        const int f = (b - NPCHUNK * NCHUNK) * 128 + t;   // [0, 65536)
        float4* dst4 = (float4*)(out + OFF_BEL + 3);
        #pragma unroll 4
        for (int k = 0; k < 32; k++) {
            const int i = f + (k << 16);
            if (i >= BEL_Q4) break;
            const int j = 3 + 4 * i;
            const int p = j >> 16;
            const int n = j & 65535;      // n == 3 (mod 4)
            float4 v;
            if (n < 65535) {
                const int  pn = __ldg(parent + n);
                const int4 p4 = __ldg((const int4*)(parent + n + 1));
                v.x = (pn   == p) ? 1.f : 0.f;
                v.y = (p4.x == p) ? 1.f : 0.f;
                v.z = (p4.y == p) ? 1.f : 0.f;
                v.w = (p4.z == p) ? 1.f : 0.f;
            } else {                      // crosses row boundary: (p,65535),(p+1,0..2)
                v.x = (__ldg(parent + 65535) == p)     ? 1.f : 0.f;
                v.y = (__ldg(parent + 0)     == p + 1) ? 1.f : 0.f;
                v.z = (__ldg(parent + 1)     == p + 1) ? 1.f : 0.f;
                v.w = (__ldg(parent + 2)     == p + 1) ? 1.f : 0.f;
            }
            dst4[i] = v;
        }
        if (b == NPCHUNK * NCHUNK && t == 0) {   // head (p=0,n=0..2) + tail (p=127,n=65535)
            out[OFF_BEL + 0] = (__ldg(parent + 0) == 0) ? 1.f : 0.f;
            out[OFF_BEL + 1] = (__ldg(parent + 1) == 0) ? 1.f : 0.f;
            out[OFF_BEL + 2] = (__ldg(parent + 2) == 0) ? 1.f : 0.f;
            out[OFF_BEL + NPART * NNODES - 1] = (__ldg(parent + NNODES - 1) == 127) ? 1.f : 0.f;
        }
        return;
    }

    // ---------------- dist blocks ----------------
    __shared__ float sm0[NPART], sm1[NPART], sm2[NPART];
    __shared__ float sdx2[NPART];
    __shared__ int   scnt[NPART];
    __shared__ int   s_cc, s_base;
    __shared__ float4 s_cond[256];
    __shared__ float swp[4][7];

    const int chunk = b & (NCHUNK - 1);
    const int pc    = b >> 8;
    const bool acc  = (pc == 0);

    sm0[t] = maxx[3 * t + 0];
    sm1[t] = maxx[3 * t + 1];
    sm2[t] = maxx[3 * t + 2];
    if (acc) { sdx2[t] = 0.f; scnt[t] = 0; if (t == 0) s_cc = 0; }
    __syncthreads();

    const int  g = chunk * 128 + t;
    const bool paired = (g < NCHUNK * 128 - 1);
    const int  na = paired ? 2 * g + 1 : 0;
    const int  nb = paired ? 2 * g + 2 : NNODES - 1;

    const float a0 = x[3 * na], a1 = x[3 * na + 1], a2 = x[3 * na + 2];
    const float b0 = x[3 * nb], b1 = x[3 * nb + 1], b2 = x[3 * nb + 2];

    if (acc) {
        const int   pa = parent[na], pb = parent[nb];
        const float qa = q[na], qb = q[nb];
        const float ia = ic[na], ib = ic[nb];
        const float nxa = fmaf(a2, a2, fmaf(a1, a1, a0 * a0));
        const float nxb = fmaf(b2, b2, fmaf(b1, b1, b0 * b0));
        const float q2a = qa * qa, q2b = qb * qb;

        float d0 = a0 - sm0[pa], d1 = a1 - sm1[pa], d2 = a2 - sm2[pa];
        atomicAdd(&sdx2[pa], fmaf(d2, d2, fmaf(d1, d1, d0 * d0)));  // native shared f32
        atomicAdd(&scnt[pa], 1);
        d0 = b0 - sm0[pb]; d1 = b1 - sm1[pb]; d2 = b2 - sm2[pb];
        atomicAdd(&sdx2[pb], fmaf(d2, d2, fmaf(d1, d1, d0 * d0)));
        atomicAdd(&scnt[pb], 1);

        if (ia > 0.f) { int p_ = atomicAdd(&s_cc, 1); s_cond[p_] = make_float4(a0, a1, a2, 0.f); }
        if (ib > 0.f) { int p_ = atomicAdd(&s_cc, 1); s_cond[p_] = make_float4(b0, b1, b2, 0.f); }

        float v[7] = { qa + qb, q2a + q2b,
                       fmaf(q2a, nxa, q2b * nxb),
                       fmaf(q2a, a0, q2b * b0),
                       fmaf(q2a, a1, q2b * b1),
                       fmaf(q2a, a2, q2b * b2),
                       nxa + nxb };
        #pragma unroll
        for (int k = 0; k < 7; k++) {
            float s = v[k];
            #pragma unroll
            for (int o = 16; o > 0; o >>= 1) s += __shfl_xor_sync(0xffffffffu, s, o);
            v[k] = s;
        }
        if ((t & 31) == 0) {
            #pragma unroll
            for (int k = 0; k < 7; k++) swp[t >> 5][k] = v[k];
        }
    }

    // ---- dist_edge: 32 rows, float2 per thread (aligned: na odd) ----
    float* dbase = out + OFF_DIST;
    const int p0 = pc * 32;
    if (paired) {
        #pragma unroll 4
        for (int pp = 0; pp < 32; pp++) {
            const int p = p0 + pp;
            const float m0 = sm0[p], m1 = sm1[p], m2 = sm2[p];
            float d0 = a0 - m0, d1 = a1 - m1, d2 = a2 - m2;
            const float da = fsqrt_ap(fmaf(d2, d2, fmaf(d1, d1, d0 * d0)));
            d0 = b0 - m0; d1 = b1 - m1; d2 = b2 - m2;
            const float db_ = fsqrt_ap(fmaf(d2, d2, fmaf(d1, d1, d0 * d0)));
            *(float2*)(dbase + p * NNODES + na) = make_float2(da, db_);
        }
    } else {
        for (int pp = 0; pp < 32; pp++) {
            const int p = p0 + pp;
            const float m0 = sm0[p], m1 = sm1[p], m2 = sm2[p];
            float d0 = a0 - m0, d1 = a1 - m1, d2 = a2 - m2;
            dbase[p * NNODES + na] = fsqrt_ap(fmaf(d2, d2, fmaf(d1, d1, d0 * d0)));
            d0 = b0 - m0; d1 = b1 - m1; d2 = b2 - m2;
            dbase[p * NNODES + nb] = fsqrt_ap(fmaf(d2, d2, fmaf(d1, d1, d0 * d0)));
        }
    }

    if (acc) {
        __syncthreads();
        if (t == 0) {
            #pragma unroll
            for (int k = 0; k < 7; k++)
                g_part_scal[chunk][k] = swp[0][k] + swp[1][k] + swp[2][k] + swp[3][k];
            s_base = (s_cc > 0) ? atomicAdd(&g_ncond, s_cc) : 0;
        }
        atomicAdd(&g_sumdx2[t], (double)sdx2[t]);
        atomicAdd(&g_cnt[t], scnt[t]);
        __syncthreads();
        const int cc = s_cc, base = s_base;
        if (t < cc) g_condx[base + t] = s_cond[t];
        if (t + 128 < cc) g_condx[base + t + 128] = s_cond[t + 128];
    }
}

// ---------------------------------------------------------------------------
// k_post, grid = 386 x 256 (R8 structure; finalize DB loop division-free):
//   blocks [0,129):   top-5 over contiguous compacted cond points (b==128: global, m=0)
//   block  129:       finalize
//   blocks [130,386): N_node gather (direct g_cnt reads)
__global__ void __launch_bounds__(256)
k_post(const float* __restrict__ maxx, const float* __restrict__ maxq,
       const int* __restrict__ parent, float* __restrict__ out) {
    const int b = blockIdx.x, t = threadIdx.x;

    if (b < NPART + 1) {
        // ---------------- top-5: contiguous coalesced scan ----------------
        float m0 = 0.f, m1 = 0.f, m2 = 0.f;
        if (b < NPART) { m0 = maxx[3 * b]; m1 = maxx[3 * b + 1]; m2 = maxx[3 * b + 2]; }
        const int nc = g_ncond;

        float tv[5] = { BIGV, BIGV, BIGV, BIGV, BIGV };
        for (int i = t; i < nc; i += 256) {
            const float4 c = g_condx[i];
            const float d0 = c.x - m0, d1 = c.y - m1, d2 = c.z - m2;
            const float d = fsqrt_ap(fmaf(d2, d2, fmaf(d1, d1, d0 * d0)));
            if (d >= EPSV && d < tv[4]) {
                tv[4] = d;
                #pragma unroll
                for (int k = 4; k > 0; k--)
                    if (tv[k] < tv[k - 1]) { float tmp = tv[k - 1]; tv[k - 1] = tv[k]; tv[k] = tmp; }
            }
        }

        __shared__ float s[256 * 5];
        #pragma unroll
        for (int k = 0; k < 5; k++) s[t * 5 + k] = tv[k];
        __syncthreads();
        for (int str = 128; str >= 1; str >>= 1) {
            if (t < str) {
                float A[5], B[5], R[5];
                #pragma unroll
                for (int k = 0; k < 5; k++) { A[k] = s[t * 5 + k]; B[k] = s[(t + str) * 5 + k]; }
                int ja = 0, jb = 0;
                #pragma unroll
                for (int k = 0; k < 5; k++) R[k] = (A[ja] <= B[jb]) ? A[ja++] : B[jb++];
                #pragma unroll
                for (int k = 0; k < 5; k++) s[t * 5 + k] = R[k];
            }
            __syncthreads();
        }
        if (t == 0) {
            float* dst = (b < NPART) ? (out + OFF_NN + b * 5) : (out + OFF_NNG);
            #pragma unroll
            for (int k = 0; k < 5; k++) dst[k] = s[k];
        }
    } else if (b == NPART + 1) {
        // ---------------- finalize ----------------
        __shared__ double sscal[7];
        __shared__ float  srms[NPART], sx0[NPART], sx1[NPART], sx2[NPART], sred[NPART];

        // scalar partials: warp w reduces scalar w over 256 chunks
        const int w = t >> 5, l = t & 31;
        if (w < 7) {
            float facc = 0.f;
            #pragma unroll
            for (int r = 0; r < 8; r++) facc += g_part_scal[l + 32 * r][w];
            double acc = (double)facc;
            #pragma unroll
            for (int o = 16; o > 0; o >>= 1)
                acc += __shfl_xor_sync(0xffffffffu, acc, o);
            if (l == 0) sscal[w] = acc;
        }
        __syncthreads();

        const double sumq = sscal[0], Bq = sscal[1], A = sscal[2];
        const double C0 = sscal[3], C1 = sscal[4], C2 = sscal[5], snx2 = sscal[6];

        if (t < NPART) {
            const float m0 = maxx[3 * t], m1 = maxx[3 * t + 1], m2 = maxx[3 * t + 2];
            const int   cnt = g_cnt[t];
            const double Npd = (double)cnt;
            const double mp2 = (double)m0 * m0 + (double)m1 * m1 + (double)m2 * m2;
            const double S = A + mp2 * Bq - 2.0 * ((double)m0 * C0 + (double)m1 * C1 + (double)m2 * C2);
            const float rms = (float)sqrt(g_sumdx2[t] / Npd);
            const double mq = (double)maxq[t];
            // particle-case sum_q quirk: whole [P,N] mailbox = P * sum(q)
            const float rmsq = (float)sqrt(mq * mq * S / (Npd * ((double)NPART * sumq)));
            out[OFF_RMS  + t] = rms;
            out[OFF_RMSQ + t] = rmsq;
            out[OFF_NP   + t] = (float)cnt;
            srms[t] = rms; sx0[t] = m0; sx1[t] = m1; sx2[t] = m2;
        }
        __syncthreads();

        // Davies-Bouldin max_j (rms_i+rms_j)/M2 — division-free running max:
        // keep best as a fraction (num, den); candidate DS/M2 beats num/den
        // iff DS*den > num*M2 (all operands >= 0, M2 > 0 guarded).
        if (t < NPART) {
            const float ri = srms[t], xi0 = sx0[t], xi1 = sx1[t], xi2 = sx2[t];
            float num = 0.f, den = 1.f;
            #pragma unroll 4
            for (int j = 0; j < NPART; j++) {
                const float e0 = xi0 - sx0[j], e1 = xi1 - sx1[j], e2 = xi2 - sx2[j];
                const float M2 = fmaf(e2, e2, fmaf(e1, e1, e0 * e0));
                const float DS = ri + srms[j];
                const bool better = (M2 > 0.f) && (DS * den > num * M2);
                num = better ? DS : num;
                den = better ? M2 : den;
            }
            sred[t] = num / den;           // single division per particle
        }
        __syncthreads();
        for (int str = 64; str >= 1; str >>= 1) {
            if (t < str) sred[t] += sred[t + str];
            __syncthreads();
        }
        if (t == 0) {
            out[OFF_DB]    = sred[0] / (float)NPART;
            out[OFF_RMSG]  = (float)sqrt(snx2 / (double)NNODES);
            out[OFF_RMSQG] = (float)sqrt(A / ((double)NNODES * sumq));
            out[OFF_NG]    = (float)NNODES;
        }
    } else {
        // ---------------- N_node gather (direct g_cnt reads) ----------------
        const int n = (b - (NPART + 2)) * 256 + t;
        out[OFF_NNODE + n] = (float)g_cnt[parent[n]];
    }
}

// ---------------------------------------------------------------------------
extern "C" void kernel_launch(void* const* d_in, const int* in_sizes, int n_in,
                              void* d_out, int out_size) {
    const float* x      = (const float*)d_in[0];
    const float* q      = (const float*)d_in[1];
    const float* ic     = (const float*)d_in[2];
    const float* maxx   = (const float*)d_in[5];
    const float* maxq   = (const float*)d_in[6];
    const int*   parent = (const int*)d_in[8];
    float* out = (float*)d_out;

    k_init<<<1, 128>>>();
    k_main<<<NPCHUNK * NCHUNK + NBELBLK, 128>>>(x, q, ic, maxx, parent, out);
    k_post<<<NPART + 2 + NNODES / 256, 256>>>(maxx, maxq, parent, out);
    (void)in_sizes; (void)n_in; (void)out_size;
}

// round 14
// speedup vs baseline: 1.2667x; 1.0469x over previous
#include <cuda_runtime.h>
#include <cstdint>

#define NNODES 65536
#define NPART  128
#define EPSV   1e-8f
#define BIGV   999.0f

// ---- output layout (flattened f32, reference tuple order) ----
#define OFF_RMS    0
#define OFF_RMSQ   128
#define OFF_NP     256
#define OFF_NN     384
#define OFF_RMSG   1024
#define OFF_RMSQG  1025
#define OFF_NG     1026
#define OFF_NNG    1027
#define OFF_DB     1032
#define OFF_NNODE  1033
#define OFF_DIST   66569
#define OFF_BEL    8455177

// belongs region: [OFF_BEL, OFF_BEL + 128*65536). OFF_BEL % 4 == 1 ->
// head of 3 scalars, 2097151 aligned float4s, tail of 1 scalar.
#define BEL_Q4     2097151
#define NCHUNK     128     // node-quad chunks (128 acc blocks x 128 quad-threads)
#define NPCHUNK    4       // particle-row chunks for dist blocks
#define NDISTBLK   (NPCHUNK * NCHUNK)   // 512
#define NBELBLK    512     // belongs fill blocks

// ---- device scratch (k_init zeroes the atomic accumulators) ----
__device__ float  g_part_scal[NCHUNK][8];  // plain stores: [0]=sum q [1]=q^2 [2]=A [3..5]=C [6]=|x|^2
__device__ double g_sumdx2[NPART];
__device__ int    g_cnt[NPART];
__device__ int    g_ncond;
__device__ float4 g_condx[NNODES];         // globally compacted, contiguous

__device__ __forceinline__ float fsqrt_ap(float x) {
    float r; asm("sqrt.approx.f32 %0, %1;" : "=f"(r) : "f"(x)); return r;
}

// ---------------------------------------------------------------------------
__global__ void k_init() {
    int t = threadIdx.x;
    if (t < NPART) { g_sumdx2[t] = 0.0; g_cnt[t] = 0; }
    if (t == 0)    g_ncond = 0;
}

// ---------------------------------------------------------------------------
// k_main, grid = 1024 x 128 threads:
//   blocks [0,512):    dist. chunk = b & 127 (128 node QUADS: nodes 4g+3..4g+6,
//                      aligned STG.128 since OFF_DIST%4==1), pc = b >> 7
//                      (32 particle rows). pc==0 blocks also accumulate.
//                      Edge thread (gg==16383) handles nodes {0,1,2,65535}.
//   blocks [512,1024): belongs fill: aligned float4 stores of (parent[n]==p).
__global__ void __launch_bounds__(128)
k_main(const float* __restrict__ x, const float* __restrict__ q,
       const float* __restrict__ ic, const float* __restrict__ maxx,
       const int* __restrict__ parent, float* __restrict__ out) {
    const int b = blockIdx.x, t = threadIdx.x;

    if (b >= NDISTBLK) {
        // ---------------- belongs fill ----------------
        const int f = (b - NDISTBLK) * 128 + t;   // [0, 65536)
        float4* dst4 = (float4*)(out + OFF_BEL + 3);
        #pragma unroll 4
        for (int k = 0; k < 32; k++) {
            const int i = f + (k << 16);
            if (i >= BEL_Q4) break;
            const int j = 3 + 4 * i;
            const int p = j >> 16;
            const int n = j & 65535;      // n == 3 (mod 4)
            float4 v;
            if (n < 65535) {
                const int  pn = __ldg(parent + n);
                const int4 p4 = __ldg((const int4*)(parent + n + 1));
                v.x = (pn   == p) ? 1.f : 0.f;
                v.y = (p4.x == p) ? 1.f : 0.f;
                v.z = (p4.y == p) ? 1.f : 0.f;
                v.w = (p4.z == p) ? 1.f : 0.f;
            } else {                      // crosses row boundary: (p,65535),(p+1,0..2)
                v.x = (__ldg(parent + 65535) == p)     ? 1.f : 0.f;
                v.y = (__ldg(parent + 0)     == p + 1) ? 1.f : 0.f;
                v.z = (__ldg(parent + 1)     == p + 1) ? 1.f : 0.f;
                v.w = (__ldg(parent + 2)     == p + 1) ? 1.f : 0.f;
            }
            dst4[i] = v;
        }
        if (b == NDISTBLK && t == 0) {   // head (p=0,n=0..2) + tail (p=127,n=65535)
            out[OFF_BEL + 0] = (__ldg(parent + 0) == 0) ? 1.f : 0.f;
            out[OFF_BEL + 1] = (__ldg(parent + 1) == 0) ? 1.f : 0.f;
            out[OFF_BEL + 2] = (__ldg(parent + 2) == 0) ? 1.f : 0.f;
            out[OFF_BEL + NPART * NNODES - 1] = (__ldg(parent + NNODES - 1) == 127) ? 1.f : 0.f;
        }
        return;
    }

    // ---------------- dist blocks ----------------
    __shared__ float sm0[NPART], sm1[NPART], sm2[NPART];
    __shared__ float sdx2[NPART];
    __shared__ int   scnt[NPART];
    __shared__ int   s_cc, s_base;
    __shared__ float4 s_cond[512];
    __shared__ float swp[4][7];

    const int chunk = b & (NCHUNK - 1);
    const int pc    = b >> 7;
    const bool acc  = (pc == 0);

    sm0[t] = maxx[3 * t + 0];
    sm1[t] = maxx[3 * t + 1];
    sm2[t] = maxx[3 * t + 2];
    if (acc) { sdx2[t] = 0.f; scnt[t] = 0; if (t == 0) s_cc = 0; }
    __syncthreads();

    const int  gg = chunk * 128 + t;                 // [0, 16384)
    const bool quad = (gg < NCHUNK * 128 - 1);
    // quad: nodes 4gg+3 .. 4gg+6 (store addr = OFF_DIST + 4gg+3 == 0 mod 4)
    // edge: nodes {0, 1, 2, 65535}
    int n0, n1, n2, n3;
    if (quad) { n0 = 4 * gg + 3; n1 = n0 + 1; n2 = n0 + 2; n3 = n0 + 3; }
    else      { n0 = 0; n1 = 1; n2 = 2; n3 = NNODES - 1; }

    const float a0 = x[3 * n0], a1 = x[3 * n0 + 1], a2 = x[3 * n0 + 2];
    const float b0 = x[3 * n1], b1 = x[3 * n1 + 1], b2 = x[3 * n1 + 2];
    const float c0 = x[3 * n2], c1 = x[3 * n2 + 1], c2 = x[3 * n2 + 2];
    const float e0 = x[3 * n3], e1 = x[3 * n3 + 1], e2 = x[3 * n3 + 2];

    if (acc) {
        const int pa = parent[n0], pb = parent[n1], pcx = parent[n2], pd = parent[n3];
        const float qa = q[n0], qb = q[n1], qc = q[n2], qd = q[n3];
        const float ia = ic[n0], ib = ic[n1], icc = ic[n2], id_ = ic[n3];
        const float nxa = fmaf(a2, a2, fmaf(a1, a1, a0 * a0));
        const float nxb = fmaf(b2, b2, fmaf(b1, b1, b0 * b0));
        const float nxc = fmaf(c2, c2, fmaf(c1, c1, c0 * c0));
        const float nxd = fmaf(e2, e2, fmaf(e1, e1, e0 * e0));
        const float q2a = qa * qa, q2b = qb * qb, q2c = qc * qc, q2d = qd * qd;

        {   // parent-particle contributions (belongs is one-hot per node)
            float d0 = a0 - sm0[pa], d1 = a1 - sm1[pa], d2 = a2 - sm2[pa];
            atomicAdd(&sdx2[pa], fmaf(d2, d2, fmaf(d1, d1, d0 * d0)));
            atomicAdd(&scnt[pa], 1);
            d0 = b0 - sm0[pb]; d1 = b1 - sm1[pb]; d2 = b2 - sm2[pb];
            atomicAdd(&sdx2[pb], fmaf(d2, d2, fmaf(d1, d1, d0 * d0)));
            atomicAdd(&scnt[pb], 1);
            d0 = c0 - sm0[pcx]; d1 = c1 - sm1[pcx]; d2 = c2 - sm2[pcx];
            atomicAdd(&sdx2[pcx], fmaf(d2, d2, fmaf(d1, d1, d0 * d0)));
            atomicAdd(&scnt[pcx], 1);
            d0 = e0 - sm0[pd]; d1 = e1 - sm1[pd]; d2 = e2 - sm2[pd];
            atomicAdd(&sdx2[pd], fmaf(d2, d2, fmaf(d1, d1, d0 * d0)));
            atomicAdd(&scnt[pd], 1);
        }

        if (ia  > 0.f) { int p_ = atomicAdd(&s_cc, 1); s_cond[p_] = make_float4(a0, a1, a2, 0.f); }
        if (ib  > 0.f) { int p_ = atomicAdd(&s_cc, 1); s_cond[p_] = make_float4(b0, b1, b2, 0.f); }
        if (icc > 0.f) { int p_ = atomicAdd(&s_cc, 1); s_cond[p_] = make_float4(c0, c1, c2, 0.f); }
        if (id_ > 0.f) { int p_ = atomicAdd(&s_cc, 1); s_cond[p_] = make_float4(e0, e1, e2, 0.f); }

        float v[7] = { (qa + qb) + (qc + qd),
                       (q2a + q2b) + (q2c + q2d),
                       fmaf(q2a, nxa, q2b * nxb) + fmaf(q2c, nxc, q2d * nxd),
                       fmaf(q2a, a0, q2b * b0) + fmaf(q2c, c0, q2d * e0),
                       fmaf(q2a, a1, q2b * b1) + fmaf(q2c, c1, q2d * e1),
                       fmaf(q2a, a2, q2b * b2) + fmaf(q2c, c2, q2d * e2),
                       (nxa + nxb) + (nxc + nxd) };
        #pragma unroll
        for (int k = 0; k < 7; k++) {
            float s = v[k];
            #pragma unroll
            for (int o = 16; o > 0; o >>= 1) s += __shfl_xor_sync(0xffffffffu, s, o);
            v[k] = s;
        }
        if ((t & 31) == 0) {
            #pragma unroll
            for (int k = 0; k < 7; k++) swp[t >> 5][k] = v[k];
        }
    }

    // ---- dist_edge: 32 rows, one aligned float4 store per thread-row ----
    float* dbase = out + OFF_DIST;
    const int p0 = pc * 32;
    if (quad) {
        #pragma unroll 4
        for (int pp = 0; pp < 32; pp++) {
            const int p = p0 + pp;
            const float m0 = sm0[p], m1 = sm1[p], m2 = sm2[p];
            float d0 = a0 - m0, d1 = a1 - m1, d2 = a2 - m2;
            const float da = fsqrt_ap(fmaf(d2, d2, fmaf(d1, d1, d0 * d0)));
            d0 = b0 - m0; d1 = b1 - m1; d2 = b2 - m2;
            const float db_ = fsqrt_ap(fmaf(d2, d2, fmaf(d1, d1, d0 * d0)));
            d0 = c0 - m0; d1 = c1 - m1; d2 = c2 - m2;
            const float dc = fsqrt_ap(fmaf(d2, d2, fmaf(d1, d1, d0 * d0)));
            d0 = e0 - m0; d1 = e1 - m1; d2 = e2 - m2;
            const float dd = fsqrt_ap(fmaf(d2, d2, fmaf(d1, d1, d0 * d0)));
            *(float4*)(dbase + p * NNODES + n0) = make_float4(da, db_, dc, dd);
        }
    } else {
        for (int pp = 0; pp < 32; pp++) {
            const int p = p0 + pp;
            const float m0 = sm0[p], m1 = sm1[p], m2 = sm2[p];
            float d0 = a0 - m0, d1 = a1 - m1, d2 = a2 - m2;
            dbase[p * NNODES + n0] = fsqrt_ap(fmaf(d2, d2, fmaf(d1, d1, d0 * d0)));
            d0 = b0 - m0; d1 = b1 - m1; d2 = b2 - m2;
            dbase[p * NNODES + n1] = fsqrt_ap(fmaf(d2, d2, fmaf(d1, d1, d0 * d0)));
            d0 = c0 - m0; d1 = c1 - m1; d2 = c2 - m2;
            dbase[p * NNODES + n2] = fsqrt_ap(fmaf(d2, d2, fmaf(d1, d1, d0 * d0)));
            d0 = e0 - m0; d1 = e1 - m1; d2 = e2 - m2;
            dbase[p * NNODES + n3] = fsqrt_ap(fmaf(d2, d2, fmaf(d1, d1, d0 * d0)));
        }
    }

    if (acc) {
        __syncthreads();
        if (t == 0) {
            #pragma unroll
            for (int k = 0; k < 7; k++)
                g_part_scal[chunk][k] = swp[0][k] + swp[1][k] + swp[2][k] + swp[3][k];
            s_base = (s_cc > 0) ? atomicAdd(&g_ncond, s_cc) : 0;
        }
        atomicAdd(&g_sumdx2[t], (double)sdx2[t]);
        atomicAdd(&g_cnt[t], scnt[t]);
        __syncthreads();
        const int cc = s_cc, base = s_base;
        for (int i = t; i < cc; i += 128) g_condx[base + i] = s_cond[i];
    }
}

// ---------------------------------------------------------------------------
// k_post, grid = 386 x 256 (R13 structure, division-free DB):
//   blocks [0,129):   top-5 over contiguous compacted cond points (b==128: global, m=0)
//   block  129:       finalize
//   blocks [130,386): N_node gather (direct g_cnt reads)
__global__ void __launch_bounds__(256)
k_post(const float* __restrict__ maxx, const float* __restrict__ maxq,
       const int* __restrict__ parent, float* __restrict__ out) {
    const int b = blockIdx.x, t = threadIdx.x;

    if (b < NPART + 1) {
        // ---------------- top-5: contiguous coalesced scan ----------------
        float m0 = 0.f, m1 = 0.f, m2 = 0.f;
        if (b < NPART) { m0 = maxx[3 * b]; m1 = maxx[3 * b + 1]; m2 = maxx[3 * b + 2]; }
        const int nc = g_ncond;

        float tv[5] = { BIGV, BIGV, BIGV, BIGV, BIGV };
        for (int i = t; i < nc; i += 256) {
            const float4 c = g_condx[i];
            const float d0 = c.x - m0, d1 = c.y - m1, d2 = c.z - m2;
            const float d = fsqrt_ap(fmaf(d2, d2, fmaf(d1, d1, d0 * d0)));
            if (d >= EPSV && d < tv[4]) {
                tv[4] = d;
                #pragma unroll
                for (int k = 4; k > 0; k--)
                    if (tv[k] < tv[k - 1]) { float tmp = tv[k - 1]; tv[k - 1] = tv[k]; tv[k] = tmp; }
            }
        }

        __shared__ float s[256 * 5];
        #pragma unroll
        for (int k = 0; k < 5; k++) s[t * 5 + k] = tv[k];
        __syncthreads();
        for (int str = 128; str >= 1; str >>= 1) {
            if (t < str) {
                float A[5], B[5], R[5];
                #pragma unroll
                for (int k = 0; k < 5; k++) { A[k] = s[t * 5 + k]; B[k] = s[(t + str) * 5 + k]; }
                int ja = 0, jb = 0;
                #pragma unroll
                for (int k = 0; k < 5; k++) R[k] = (A[ja] <= B[jb]) ? A[ja++] : B[jb++];
                #pragma unroll
                for (int k = 0; k < 5; k++) s[t * 5 + k] = R[k];
            }
            __syncthreads();
        }
        if (t == 0) {
            float* dst = (b < NPART) ? (out + OFF_NN + b * 5) : (out + OFF_NNG);
            #pragma unroll
            for (int k = 0; k < 5; k++) dst[k] = s[k];
        }
    } else if (b == NPART + 1) {
        // ---------------- finalize ----------------
        __shared__ double sscal[7];
        __shared__ float  srms[NPART], sx0[NPART], sx1[NPART], sx2[NPART], sred[NPART];

        // scalar partials: warp w reduces scalar w over 128 chunks
        const int w = t >> 5, l = t & 31;
        if (w < 7) {
            float facc = 0.f;
            #pragma unroll
            for (int r = 0; r < 4; r++) facc += g_part_scal[l + 32 * r][w];
            double acc = (double)facc;
            #pragma unroll
            for (int o = 16; o > 0; o >>= 1)
                acc += __shfl_xor_sync(0xffffffffu, acc, o);
            if (l == 0) sscal[w] = acc;
        }
        __syncthreads();

        const double sumq = sscal[0], Bq = sscal[1], A = sscal[2];
        const double C0 = sscal[3], C1 = sscal[4], C2 = sscal[5], snx2 = sscal[6];

        if (t < NPART) {
            const float m0 = maxx[3 * t], m1 = maxx[3 * t + 1], m2 = maxx[3 * t + 2];
            const int   cnt = g_cnt[t];
            const double Npd = (double)cnt;
            const double mp2 = (double)m0 * m0 + (double)m1 * m1 + (double)m2 * m2;
            const double S = A + mp2 * Bq - 2.0 * ((double)m0 * C0 + (double)m1 * C1 + (double)m2 * C2);
            const float rms = (float)sqrt(g_sumdx2[t] / Npd);
            const double mq = (double)maxq[t];
            // particle-case sum_q quirk: whole [P,N] mailbox = P * sum(q)
            const float rmsq = (float)sqrt(mq * mq * S / (Npd * ((double)NPART * sumq)));
            out[OFF_RMS  + t] = rms;
            out[OFF_RMSQ + t] = rmsq;
            out[OFF_NP   + t] = (float)cnt;
            srms[t] = rms; sx0[t] = m0; sx1[t] = m1; sx2[t] = m2;
        }
        __syncthreads();

        // Davies-Bouldin max_j (rms_i+rms_j)/M2 — division-free running max.
        if (t < NPART) {
            const float ri = srms[t], xi0 = sx0[t], xi1 = sx1[t], xi2 = sx2[t];
            float num = 0.f, den = 1.f;
            #pragma unroll 4
            for (int j = 0; j < NPART; j++) {
                const float f0 = xi0 - sx0[j], f1 = xi1 - sx1[j], f2 = xi2 - sx2[j];
                const float M2 = fmaf(f2, f2, fmaf(f1, f1, f0 * f0));
                const float DS = ri + srms[j];
                const bool better = (M2 > 0.f) && (DS * den > num * M2);
                num = better ? DS : num;
                den = better ? M2 : den;
            }
            sred[t] = num / den;           // single division per particle
        }
        __syncthreads();
        for (int str = 64; str >= 1; str >>= 1) {
            if (t < str) sred[t] += sred[t + str];
            __syncthreads();
        }
        if (t == 0) {
            out[OFF_DB]    = sred[0] / (float)NPART;
            out[OFF_RMSG]  = (float)sqrt(snx2 / (double)NNODES);
            out[OFF_RMSQG] = (float)sqrt(A / ((double)NNODES * sumq));
            out[OFF_NG]    = (float)NNODES;
        }
    } else {
        // ---------------- N_node gather (direct g_cnt reads) ----------------
        const int n = (b - (NPART + 2)) * 256 + t;
        out[OFF_NNODE + n] = (float)g_cnt[parent[n]];
    }
}

// ---------------------------------------------------------------------------
extern "C" void kernel_launch(void* const* d_in, const int* in_sizes, int n_in,
                              void* d_out, int out_size) {
    const float* x      = (const float*)d_in[0];
    const float* q      = (const float*)d_in[1];
    const float* ic     = (const float*)d_in[2];
    const float* maxx   = (const float*)d_in[5];
    const float* maxq   = (const float*)d_in[6];
    const int*   parent = (const int*)d_in[8];
    float* out = (float*)d_out;

    k_init<<<1, 128>>>();
    k_main<<<NDISTBLK + NBELBLK, 128>>>(x, q, ic, maxx, parent, out);
    k_post<<<NPART + 2 + NNODES / 256, 256>>>(maxx, maxq, parent, out);
    (void)in_sizes; (void)n_in; (void)out_size;
}